// round 3
// baseline (speedup 1.0000x reference)
#include <cuda_runtime.h>
#include <cstring>
#include <cstdint>

// Problem constants
constexpr int NB   = 8;
constexpr int CIN  = 64;
constexpr int HH   = 128;
constexpr int WWI  = 128;
constexpr int COUT = 64;
constexpr int KK   = 9;
constexpr int HW   = HH * WWI;          // 16384
constexpr int WELEMS = COUT * CIN * KK; // 36864

// Scratch (device globals: allocation-free rule)
__device__ float g_xt[NB * HH * WWI * CIN];   // NHWC transposed x (33.5 MB)
__device__ float g_wq[KK * CIN * COUT];       // quantized weight, [k][cin][cout]

// ---------------------------------------------------------------------------
// Kernel 1: symmetric 8-bit weight quantization (forward of STE) + relayout
// ---------------------------------------------------------------------------
__global__ void quant_kernel(const float* __restrict__ w) {
    __shared__ float red[1024];
    const int t = threadIdx.x;
    float m = 0.f;
    for (int i = t; i < WELEMS; i += 1024) m = fmaxf(m, fabsf(w[i]));
    red[t] = m;
    __syncthreads();
    for (int s = 512; s > 0; s >>= 1) {
        if (t < s) red[t] = fmaxf(red[t], red[t + s]);
        __syncthreads();
    }
    const float scale = fmaxf(red[0], 1e-8f) / 127.f;
    for (int i = t; i < WELEMS; i += 1024) {
        float q = rintf(w[i] / scale);          // round half-to-even, same as jnp.round
        q = fminf(fmaxf(q, -128.f), 127.f) * scale;
        const int k  = i % 9;
        const int ci = (i / 9) % 64;
        const int co = i / 576;
        g_wq[(k * 64 + ci) * 64 + co] = q;
    }
}

// ---------------------------------------------------------------------------
// Kernel 2: transpose x [N,C,H,W] -> g_xt [N,H,W,C]
// ---------------------------------------------------------------------------
__global__ void transpose_kernel(const float* __restrict__ x) {
    __shared__ float tb[128 * 65];
    const int h = blockIdx.x, n = blockIdx.y, t = threadIdx.x;
    const float* xp = x + (size_t)n * 64 * HW + h * 128;   // + c*16384 + w
    for (int i = t; i < 8192; i += 256) {
        const int c = i >> 7, wv = i & 127;
        tb[wv * 65 + c] = xp[c * HW + wv];
    }
    __syncthreads();
    float* op = g_xt + ((size_t)n * 128 + h) * 128 * 64;
    for (int i = t; i < 8192; i += 256) {
        const int wv = i >> 6, c = i & 63;
        op[wv * 64 + c] = tb[wv * 65 + c];
    }
}

// ---------------------------------------------------------------------------
// Kernel 3: deformable conv main kernel. One block per (ho, n) output row.
// ---------------------------------------------------------------------------
constexpr int WS_FLOATS = KK * CIN * COUT;   // 36864 floats (147456 B)
constexpr int SB_PITCH  = 132;               // padded pitch for sampled tile
constexpr int SB_FLOATS = 64 * SB_PITCH;     // 8448 floats per buffer
constexpr int SMEM_BYTES = (WS_FLOATS + 2 * SB_FLOATS) * 4;   // 215040 B

__device__ __forceinline__ unsigned long long fma2(unsigned long long a,
                                                   unsigned long long b,
                                                   unsigned long long c) {
    unsigned long long d;
    asm("fma.rn.f32x2 %0, %1, %2, %3;" : "=l"(d) : "l"(a), "l"(b), "l"(c));
    return d;
}
__device__ __forceinline__ unsigned long long dup2(float s) {
    float2 t = make_float2(s, s);
    unsigned long long d;
    memcpy(&d, &t, 8);
    return d;
}

__global__ __launch_bounds__(512, 1)
void main_kernel(const float* __restrict__ offset, float* __restrict__ out) {
    extern __shared__ float sm[];
    float* Ws  = sm;                 // full quantized weight, [k][cin][cout]
    float* sb0 = sm + WS_FLOATS;     // double-buffered sampled tile [cin][132]

    const int t  = threadIdx.x;
    const int ho = blockIdx.x;
    const int n  = blockIdx.y;

    // stage all weights into smem
    {
        const float4* src = reinterpret_cast<const float4*>(g_wq);
        float4* dst = reinterpret_cast<float4*>(Ws);
        for (int i = t; i < WS_FLOATS / 4; i += 512) dst[i] = src[i];
    }

    // gather-stage mapping: 128 pixels x 4 cin-blocks of 16
    const int gpix = t & 127;
    const int gcb  = (t >> 7) << 4;
    // gemm mapping: 32 pix-quads x 8 cout-groups(8 couts) x 2 cin halves
    const int pg4 = t & 31;
    const int cg  = (t >> 5) & 7;
    const int kc  = t >> 8;

    float4 g[4];

    auto gather = [&](int k) {
        const int obase = ((n * 18 + 2 * k) * 128 + ho) * 128 + gpix;
        const float oy = __ldg(offset + obase);
        const float ox = __ldg(offset + obase + HW);
        const float py = (float)(ho + (k / 3) - 1) + oy;
        const float px = (float)(gpix + (k % 3) - 1) + ox;
        const float fy = floorf(py), fx = floorf(px);
        const float dy = py - fy, dx = px - fx;
        const int y0 = (int)fy, x0 = (int)fx;
        const float wy0 = 1.f - dy, wx0 = 1.f - dx;
        g[0] = make_float4(0.f, 0.f, 0.f, 0.f);
        g[1] = g[0]; g[2] = g[0]; g[3] = g[0];
        const float* xb = g_xt + (size_t)n * (128 * 128 * 64) + gcb;
#pragma unroll
        for (int cidx = 0; cidx < 4; cidx++) {
            const int yy = y0 + (cidx >> 1);
            const int xx = x0 + (cidx & 1);
            float wv = ((cidx >> 1) ? dy : wy0) * ((cidx & 1) ? dx : wx0);
            const bool valid = (yy >= 0) && (yy < 128) && (xx >= 0) && (xx < 128);
            wv = valid ? wv : 0.f;
            const int yc = min(max(yy, 0), 127), xc = min(max(xx, 0), 127);
            const float4* p = reinterpret_cast<const float4*>(xb + (yc * 128 + xc) * 64);
#pragma unroll
            for (int j = 0; j < 4; j++) {
                const float4 a = p[j];
                g[j].x += wv * a.x; g[j].y += wv * a.y;
                g[j].z += wv * a.z; g[j].w += wv * a.w;
            }
        }
    };

    auto sts = [&](float* buf) {
        float* q = buf + gpix;
#pragma unroll
        for (int j = 0; j < 4; j++) {
            q[(gcb + 4 * j + 0) * SB_PITCH] = g[j].x;
            q[(gcb + 4 * j + 1) * SB_PITCH] = g[j].y;
            q[(gcb + 4 * j + 2) * SB_PITCH] = g[j].z;
            q[(gcb + 4 * j + 3) * SB_PITCH] = g[j].w;
        }
    };

    unsigned long long acc[16];
#pragma unroll
    for (int i = 0; i < 16; i++) acc[i] = 0ULL;

    gather(0);
    sts(sb0);
    __syncthreads();

#pragma unroll 1
    for (int k = 0; k < 9; k++) {
        if (k < 8) gather(k + 1);   // global loads in flight during GEMM below

        const float* sr = sb0 + (k & 1) * SB_FLOATS + 4 * pg4 + kc * 32 * SB_PITCH;
        const float* wk = Ws + k * 4096 + cg * 8 + kc * 32 * 64;
#pragma unroll 2
        for (int ci = 0; ci < 32; ci++) {
            const float4 s = *reinterpret_cast<const float4*>(sr + ci * SB_PITCH);
            const ulonglong2 w0 = *reinterpret_cast<const ulonglong2*>(wk + ci * 64);
            const ulonglong2 w1 = *reinterpret_cast<const ulonglong2*>(wk + ci * 64 + 4);
            const unsigned long long a0 = dup2(s.x);
            const unsigned long long a1 = dup2(s.y);
            const unsigned long long a2 = dup2(s.z);
            const unsigned long long a3 = dup2(s.w);
            acc[0]  = fma2(a0, w0.x, acc[0]);  acc[1]  = fma2(a0, w0.y, acc[1]);
            acc[2]  = fma2(a0, w1.x, acc[2]);  acc[3]  = fma2(a0, w1.y, acc[3]);
            acc[4]  = fma2(a1, w0.x, acc[4]);  acc[5]  = fma2(a1, w0.y, acc[5]);
            acc[6]  = fma2(a1, w1.x, acc[6]);  acc[7]  = fma2(a1, w1.y, acc[7]);
            acc[8]  = fma2(a2, w0.x, acc[8]);  acc[9]  = fma2(a2, w0.y, acc[9]);
            acc[10] = fma2(a2, w1.x, acc[10]); acc[11] = fma2(a2, w1.y, acc[11]);
            acc[12] = fma2(a3, w0.x, acc[12]); acc[13] = fma2(a3, w0.y, acc[13]);
            acc[14] = fma2(a3, w1.x, acc[14]); acc[15] = fma2(a3, w1.y, acc[15]);
        }

        if (k < 8) sts(sb0 + ((k + 1) & 1) * SB_FLOATS);
        __syncthreads();
    }

    // Epilogue: combine cin halves via smem, then coalesced float4 stores.
    float* ob = sb0;   // 64 x SB_PITCH staging, free after last sync
    if (kc == 0) {
#pragma unroll
        for (int p = 0; p < 4; p++)
#pragma unroll
            for (int cp = 0; cp < 4; cp++) {
                float2 v; memcpy(&v, &acc[p * 4 + cp], 8);
                const int pix = 4 * pg4 + p, cout = cg * 8 + 2 * cp;
                ob[cout * SB_PITCH + pix]       = v.x;
                ob[(cout + 1) * SB_PITCH + pix] = v.y;
            }
    }
    __syncthreads();
    if (kc == 1) {
#pragma unroll
        for (int p = 0; p < 4; p++)
#pragma unroll
            for (int cp = 0; cp < 4; cp++) {
                float2 v; memcpy(&v, &acc[p * 4 + cp], 8);
                const int pix = 4 * pg4 + p, cout = cg * 8 + 2 * cp;
                ob[cout * SB_PITCH + pix]       += v.x;
                ob[(cout + 1) * SB_PITCH + pix] += v.y;
            }
    }
    __syncthreads();

    float* outp = out + (size_t)n * 64 * HW + ho * 128;
#pragma unroll
    for (int r = 0; r < 4; r++) {
        const int idx = r * 512 + t;          // 2048 float4 groups = 64 couts * 32
        const int cout = idx >> 5;
        const int p4 = (idx & 31) << 2;
        const float4 v = *reinterpret_cast<const float4*>(ob + cout * SB_PITCH + p4);
        *reinterpret_cast<float4*>(outp + cout * HW + p4) = v;
    }
}

// ---------------------------------------------------------------------------
extern "C" void kernel_launch(void* const* d_in, const int* in_sizes, int n_in,
                              void* d_out, int out_size) {
    const float* x      = (const float*)d_in[0];
    const float* offset = (const float*)d_in[1];
    const float* weight = (const float*)d_in[2];
    float* out = (float*)d_out;

    cudaFuncSetAttribute(main_kernel, cudaFuncAttributeMaxDynamicSharedMemorySize,
                         SMEM_BYTES);

    quant_kernel<<<1, 1024>>>(weight);
    transpose_kernel<<<dim3(HH, NB), 256>>>(x);
    main_kernel<<<dim3(HH, NB), 512, SMEM_BYTES>>>(offset, out);
}

// round 5
// speedup vs baseline: 3.3660x; 3.3660x over previous
#include <cuda_runtime.h>
#include <cuda_fp16.h>
#include <cstdint>
#include <cstring>

// ---------------------------------------------------------------------------
// Problem constants
// ---------------------------------------------------------------------------
constexpr int NB   = 8;
constexpr int HH   = 128;
constexpr int HW   = 128 * 128;           // 16384
constexpr int WELEMS = 64 * 64 * 9;       // 36864

// Scratch (device globals — allocation-free rule)
__device__ __half g_xh[NB * HH * 128 * 64];   // x as NHWC fp16 (16.8 MB)
__device__ __half g_wh[9 * 64 * 64];          // quantized int weights fp16, SW128-swizzled 8KB/tap
__device__ float  g_scale;
__device__ unsigned int g_absmax_bits;

// ---------------------------------------------------------------------------
// Helpers
// ---------------------------------------------------------------------------
__device__ __forceinline__ uint32_t smem_u32(const void* p) {
    uint32_t a;
    asm("{ .reg .u64 t; cvta.to.shared.u64 t, %1; cvt.u32.u64 %0, t; }" : "=r"(a) : "l"(p));
    return a;
}

#define LDSM4(r0, r1, r2, r3, addr)                                           \
    asm volatile("ldmatrix.sync.aligned.m8n8.x4.shared.b16 {%0,%1,%2,%3}, [%4];" \
                 : "=r"(r0), "=r"(r1), "=r"(r2), "=r"(r3) : "r"(addr))

#define MMA16816(d, a0, a1, a2, a3, b0, b1)                                   \
    asm volatile("mma.sync.aligned.m16n8k16.row.col.f32.f16.f16.f32 "         \
                 "{%0,%1,%2,%3},{%4,%5,%6,%7},{%8,%9},{%0,%1,%2,%3};"          \
                 : "+f"((d)[0]), "+f"((d)[1]), "+f"((d)[2]), "+f"((d)[3])      \
                 : "r"(a0), "r"(a1), "r"(a2), "r"(a3), "r"(b0), "r"(b1))

// ---------------------------------------------------------------------------
// Prologue kernels
// ---------------------------------------------------------------------------
__global__ void reset_kernel() { g_absmax_bits = 0u; }

__global__ void absmax_kernel(const float* __restrict__ w) {
    __shared__ float red[256];
    const int t = threadIdx.x;
    const int i = blockIdx.x * 256 + t;
    red[t] = (i < WELEMS) ? fabsf(w[i]) : 0.f;
    __syncthreads();
    for (int s = 128; s > 0; s >>= 1) {
        if (t < s) red[t] = fmaxf(red[t], red[t + s]);
        __syncthreads();
    }
    if (t == 0) atomicMax(&g_absmax_bits, __float_as_uint(red[0]));  // nonneg: uint order ok
}

__global__ void wconv_kernel(const float* __restrict__ w) {
    const float scale = fmaxf(__uint_as_float(g_absmax_bits), 1e-8f) / 127.f;
    const int i = blockIdx.x * 256 + threadIdx.x;
    if (i == 0) g_scale = scale;
    if (i >= WELEMS) return;
    float q = rintf(w[i] / scale);                 // round-half-even = jnp.round
    q = fminf(fmaxf(q, -128.f), 127.f);            // integer, exact in fp16
    const int k = i % 9, ci = (i / 9) % 64, co = i / 576;
    uint32_t off = (uint32_t)(co * 128 + ci * 2);  // B tile: row=cout(128B), col=cin
    off ^= (off >> 3) & 0x70;                      // SW128 swizzle
    g_wh[(k * 8192 + off) >> 1] = __float2half_rn(q);
}

__global__ void xcvt_kernel(const float* __restrict__ x) {
    __shared__ float tb[128 * 65];
    const int h = blockIdx.x, n = blockIdx.y, t = threadIdx.x;
    const float* xp = x + (size_t)n * 64 * HW + h * 128;
    for (int i = t; i < 8192; i += 256) {
        const int c = i >> 7, wv = i & 127;
        tb[wv * 65 + c] = xp[c * HW + wv];
    }
    __syncthreads();
    __half* op = g_xh + ((size_t)n * 128 + h) * 128 * 64;
    for (int i = t; i < 8192; i += 256) {
        const int wv = i >> 6, c = i & 63;
        op[wv * 64 + c] = __float2half_rn(tb[wv * 65 + c]);
    }
}

// ---------------------------------------------------------------------------
// Main kernel: one CTA (256 thr, 8 warps) per (ho, n) output row.
// smem: A double buffer 2x16KB (reused as 33KB f32 epilogue) | W 72KB |
//       per-(tap,pixel) params: 4 byte-offsets (int4) + 4 fp16 weights (uint2)
// ---------------------------------------------------------------------------
constexpr int SMEM_A0   = 0;
constexpr int SMEM_A1   = 16384;
constexpr int SMEM_W    = 34816;                 // EPI f32 needs [0, 33792)
constexpr int SMEM_POFF = 34816 + 73728;         // 108544, 1152 * 16B
constexpr int SMEM_PWH  = 108544 + 18432;        // 126976, 1152 * 8B
constexpr int SMEM_BYTES = 126976 + 9216;        // 136192 (~133 KB) -> 1 CTA/SM

__global__ void __launch_bounds__(256, 1)
main_kernel(const float* __restrict__ offset, float* __restrict__ out) {
    extern __shared__ char smem[];
    const uint32_t sb = smem_u32(smem);
    const int t = threadIdx.x;
    const int lane = t & 31, w = t >> 5;
    const int ho = blockIdx.x, n = blockIdx.y;

    // Stage all 9 pre-swizzled weight tiles (72 KB) into smem
    {
        const uint4* src = reinterpret_cast<const uint4*>(g_wh);
        uint4* dst = reinterpret_cast<uint4*>(smem + SMEM_W);
        for (int i = t; i < 73728 / 16; i += 256) dst[i] = src[i];
    }

    // Precompute per-(tap,pixel): 4 clamped corner byte-offsets + 4 masked fp16 weights
    int4*  POFF = reinterpret_cast<int4*>(smem + SMEM_POFF);
    uint2* PWH  = reinterpret_cast<uint2*>(smem + SMEM_PWH);
    for (int idx = t; idx < 1152; idx += 256) {
        const int k = idx >> 7, p = idx & 127;
        const int ob = ((n * 18 + 2 * k) * 128 + ho) * 128 + p;
        const float oy = __ldg(offset + ob);
        const float ox = __ldg(offset + ob + HW);
        const float py = (float)(ho + k / 3 - 1) + oy;
        const float px = (float)(p + k % 3 - 1) + ox;
        const float fy = floorf(py), fx = floorf(px);
        const float dy = py - fy, dx = px - fx;
        const int y0 = (int)fy, x0 = (int)fx;
        float wv[4]; int ofs[4];
#pragma unroll
        for (int cn = 0; cn < 4; cn++) {
            const int yy = y0 + (cn >> 1), xx = x0 + (cn & 1);
            float ww = ((cn >> 1) ? dy : 1.f - dy) * ((cn & 1) ? dx : 1.f - dx);
            const bool valid = ((unsigned)yy < 128u) && ((unsigned)xx < 128u);
            wv[cn] = valid ? ww : 0.f;
            const int yc = min(max(yy, 0), 127), xc = min(max(xx, 0), 127);
            ofs[cn] = (yc * 128 + xc) * 128;     // byte offset into NHWC fp16 image
        }
        POFF[idx] = make_int4(ofs[0], ofs[1], ofs[2], ofs[3]);
        const half2 wlo = __floats2half2_rn(wv[0], wv[1]);
        const half2 whi = __floats2half2_rn(wv[2], wv[3]);
        uint2 pw;
        pw.x = *reinterpret_cast<const uint32_t*>(&wlo);
        pw.y = *reinterpret_cast<const uint32_t*>(&whi);
        PWH[idx] = pw;
    }
    __syncthreads();

    const char* xbb = reinterpret_cast<const char*>(g_xh + (size_t)n * (128 * 128 * 64));
    const int c = t & 7;                          // 16B chunk within pixel line

    // ldmatrix lane addressing (SW128: xor term depends only on row low bits)
    const int lt = lane >> 3, lr = lane & 7;
    const int rowA = 16 * w + (lt & 1) * 8 + lr;
    const uint32_t xrA = (uint32_t)(rowA & 7) << 4;
    const int rowB = (lt & 1) * 8 + lr;
    const uint32_t xrB = (uint32_t)(rowB & 7) << 4;
    const uint32_t cgrp = (uint32_t)(lt >> 1) * 16;
    const uint32_t aRow = (uint32_t)rowA * 128;
    const uint32_t bRow = (uint32_t)rowB * 128;

    float acc[8][4];
#pragma unroll
    for (int i = 0; i < 8; i++)
#pragma unroll
        for (int j = 0; j < 4; j++) acc[i][j] = 0.f;

    for (int k = 0; k < 9; k++) {
        const uint32_t abuf = sb + ((k & 1) ? SMEM_A1 : SMEM_A0);
        char* abufp = smem + ((k & 1) ? SMEM_A1 : SMEM_A0);
        const int pbase = k << 7;

        // ---- gather: batch all 16 corner LDG.128 (MLP=16) ----
        uint4 v[4][4];
        uint2 wh4[4];
#pragma unroll
        for (int a = 0; a < 4; a++) {
            const int p = (a * 256 + t) >> 3;
            const int4 ofs = POFF[pbase + p];
            wh4[a] = PWH[pbase + p];
            v[a][0] = *reinterpret_cast<const uint4*>(xbb + ofs.x + c * 16);
            v[a][1] = *reinterpret_cast<const uint4*>(xbb + ofs.y + c * 16);
            v[a][2] = *reinterpret_cast<const uint4*>(xbb + ofs.z + c * 16);
            v[a][3] = *reinterpret_cast<const uint4*>(xbb + ofs.w + c * 16);
        }

        // ---- bilinear in half2, store to swizzled A tile ----
#pragma unroll
        for (int a = 0; a < 4; a++) {
            const int p = (a * 256 + t) >> 3;
            const half2 wlo = *reinterpret_cast<const half2*>(&wh4[a].x);
            const half2 whi = *reinterpret_cast<const half2*>(&wh4[a].y);
            const half2 w00 = __low2half2(wlo),  w01 = __high2half2(wlo);
            const half2 w10 = __low2half2(whi),  w11 = __high2half2(whi);
            const half2* q0 = reinterpret_cast<const half2*>(&v[a][0]);
            const half2* q1 = reinterpret_cast<const half2*>(&v[a][1]);
            const half2* q2 = reinterpret_cast<const half2*>(&v[a][2]);
            const half2* q3 = reinterpret_cast<const half2*>(&v[a][3]);
            half2 s[4];
#pragma unroll
            for (int j = 0; j < 4; j++) {
                s[j] = __hmul2(w00, q0[j]);
                s[j] = __hfma2(w01, q1[j], s[j]);
                s[j] = __hfma2(w10, q2[j], s[j]);
                s[j] = __hfma2(w11, q3[j], s[j]);
            }
            uint32_t boff = (uint32_t)(p * 128 + c * 16);
            boff ^= (boff >> 3) & 0x70;
            uint4 ov;
            ov.x = *reinterpret_cast<const uint32_t*>(&s[0]);
            ov.y = *reinterpret_cast<const uint32_t*>(&s[1]);
            ov.z = *reinterpret_cast<const uint32_t*>(&s[2]);
            ov.w = *reinterpret_cast<const uint32_t*>(&s[3]);
            *reinterpret_cast<uint4*>(abufp + boff) = ov;
        }
        __syncthreads();

        // ---- tap-k GEMM: per warp 16 pix x 64 cout x 64 cin via HMMA ----
        const uint32_t wk = sb + SMEM_W + k * 8192;
#pragma unroll
        for (int kc = 0; kc < 4; kc++) {
            const uint32_t byte = (uint32_t)(kc * 32) + cgrp;
            uint32_t a0, a1, a2, a3;
            LDSM4(a0, a1, a2, a3, abuf + aRow + (byte ^ xrA));
            const uint32_t bb = byte ^ xrB;
#pragma unroll
            for (int j = 0; j < 4; j++) {
                uint32_t b0, b1, b2, b3;
                LDSM4(b0, b1, b2, b3, wk + bRow + (uint32_t)j * 2048 + bb);
                MMA16816(acc[2 * j],     a0, a1, a2, a3, b0, b2);
                MMA16816(acc[2 * j + 1], a0, a1, a2, a3, b1, b3);
            }
        }
    }
    __syncthreads();   // all LDSM reads done before epilogue reuses A region

    // ---- epilogue: scale, transpose through smem, coalesced float4 stores ----
    const float scale = g_scale;
    float* EPI = reinterpret_cast<float*>(smem);      // [64 cout][pitch 132]
    const int gr = lane >> 2, ci2 = (lane & 3) * 2, p0 = 16 * w;
#pragma unroll
    for (int nb = 0; nb < 8; nb++) {
        const int co = nb * 8 + ci2;
        EPI[co * 132 + p0 + gr]           = acc[nb][0] * scale;
        EPI[(co + 1) * 132 + p0 + gr]     = acc[nb][1] * scale;
        EPI[co * 132 + p0 + gr + 8]       = acc[nb][2] * scale;
        EPI[(co + 1) * 132 + p0 + gr + 8] = acc[nb][3] * scale;
    }
    __syncthreads();
    float* op = out + (size_t)n * 64 * HW + ho * 128;
#pragma unroll
    for (int r = 0; r < 8; r++) {
        const int idx = r * 256 + t;                  // 2048 float4 = 64 couts x 32
        const int co = idx >> 5, p4 = (idx & 31) * 4;
        const float4 vv = *reinterpret_cast<const float4*>(EPI + co * 132 + p4);
        *reinterpret_cast<float4*>(op + co * HW + p4) = vv;
    }
}

// ---------------------------------------------------------------------------
extern "C" void kernel_launch(void* const* d_in, const int* in_sizes, int n_in,
                              void* d_out, int out_size) {
    const float* x      = (const float*)d_in[0];
    const float* offset = (const float*)d_in[1];
    const float* weight = (const float*)d_in[2];
    float* out = (float*)d_out;

    cudaFuncSetAttribute(main_kernel, cudaFuncAttributeMaxDynamicSharedMemorySize,
                         SMEM_BYTES);

    reset_kernel<<<1, 1>>>();
    absmax_kernel<<<(WELEMS + 255) / 256, 256>>>(weight);
    wconv_kernel<<<(WELEMS + 255) / 256, 256>>>(weight);
    xcvt_kernel<<<dim3(HH, NB), 256>>>(x);
    main_kernel<<<dim3(HH, NB), 256, SMEM_BYTES>>>(offset, out);
}

// round 7
// speedup vs baseline: 4.7142x; 1.4005x over previous
#include <cuda_runtime.h>
#include <cuda_fp16.h>
#include <cstdint>
#include <cstring>

// ---------------------------------------------------------------------------
// Problem constants
// ---------------------------------------------------------------------------
constexpr int NB   = 8;
constexpr int HH   = 128;
constexpr int HW   = 128 * 128;           // 16384
constexpr int WELEMS = 64 * 64 * 9;       // 36864

// Scratch (device globals — allocation-free rule)
__device__ __half g_xh[NB * HH * 128 * 64];   // x as NHWC fp16 (16.8 MB)
__device__ __half g_wh[9 * 64 * 64];          // quantized int weights fp16, SW128-swizzled 8KB/tap
__device__ float  g_scale;

// ---------------------------------------------------------------------------
// Helpers
// ---------------------------------------------------------------------------
__device__ __forceinline__ uint32_t smem_u32(const void* p) {
    uint32_t a;
    asm("{ .reg .u64 t; cvta.to.shared.u64 t, %1; cvt.u32.u64 %0, t; }" : "=r"(a) : "l"(p));
    return a;
}

#define LDSM4(r0, r1, r2, r3, addr)                                           \
    asm volatile("ldmatrix.sync.aligned.m8n8.x4.shared.b16 {%0,%1,%2,%3}, [%4];" \
                 : "=r"(r0), "=r"(r1), "=r"(r2), "=r"(r3) : "r"(addr))

#define MMA16816(d, a0, a1, a2, a3, b0, b1)                                   \
    asm volatile("mma.sync.aligned.m16n8k16.row.col.f32.f16.f16.f32 "         \
                 "{%0,%1,%2,%3},{%4,%5,%6,%7},{%8,%9},{%0,%1,%2,%3};"          \
                 : "+f"((d)[0]), "+f"((d)[1]), "+f"((d)[2]), "+f"((d)[3])      \
                 : "r"(a0), "r"(a1), "r"(a2), "r"(a3), "r"(b0), "r"(b1))

// ---------------------------------------------------------------------------
// Prologue kernel 1: absmax + scale (single block, no atomics, no reset pass)
// ---------------------------------------------------------------------------
__global__ void absmax_kernel(const float* __restrict__ w) {
    __shared__ float red[1024];
    const int t = threadIdx.x;
    const float4* w4 = reinterpret_cast<const float4*>(w);
    float m = 0.f;
    for (int i = t; i < WELEMS / 4; i += 1024) {
        const float4 v = __ldg(w4 + i);
        m = fmaxf(m, fmaxf(fmaxf(fabsf(v.x), fabsf(v.y)), fmaxf(fabsf(v.z), fabsf(v.w))));
    }
    red[t] = m;
    __syncthreads();
    for (int s = 512; s > 0; s >>= 1) {
        if (t < s) red[t] = fmaxf(red[t], red[t + s]);
        __syncthreads();
    }
    if (t == 0) g_scale = fmaxf(red[0], 1e-8f) / 127.f;
}

// Prologue kernel 2: quantize + relayout (SW128-swizzled, [k][cout row][cin])
__global__ void wconv_kernel(const float* __restrict__ w) {
    const float scale = g_scale;
    const int i = blockIdx.x * 256 + threadIdx.x;
    if (i >= WELEMS) return;
    float q = rintf(w[i] / scale);                 // round-half-even = jnp.round
    q = fminf(fmaxf(q, -128.f), 127.f);            // integer, exact in fp16
    const int k = i % 9, ci = (i / 9) % 64, co = i / 576;
    uint32_t off = (uint32_t)(co * 128 + ci * 2);  // B tile: row=cout(128B), col=cin
    off ^= (off >> 3) & 0x70;                      // SW128 swizzle
    g_wh[(k * 8192 + off) >> 1] = __float2half_rn(q);
}

// Prologue kernel 3: x [N,C,H,W] f32 -> g_xh [N,H,W,C] fp16 (vectorized)
__global__ void xcvt_kernel(const float* __restrict__ x) {
    __shared__ float tb[128 * 65];
    const int h = blockIdx.x, n = blockIdx.y, t = threadIdx.x;
    const float* xp = x + (size_t)n * 64 * HW + h * 128;
    for (int i = t; i < 2048; i += 256) {          // 64c x 32 float4, coalesced 512B/warp
        const int c = i >> 5, q = i & 31;
        const float4 v = __ldg(reinterpret_cast<const float4*>(xp + c * HW) + q);
        float* tq = tb + (q * 4) * 65 + c;
        tq[0] = v.x; tq[65] = v.y; tq[130] = v.z; tq[195] = v.w;
    }
    __syncthreads();
    __half* op = g_xh + ((size_t)n * 128 + h) * 128 * 64;
    for (int i = t; i < 1024; i += 256) {          // 128w x 8 groups of 8 channels
        const int wv = i >> 3, cg = i & 7;
        const float* src = tb + wv * 65 + cg * 8;  // conflict-free: bank = wv + 8cg + j
        const half2 h0 = __floats2half2_rn(src[0], src[1]);
        const half2 h1 = __floats2half2_rn(src[2], src[3]);
        const half2 h2 = __floats2half2_rn(src[4], src[5]);
        const half2 h3 = __floats2half2_rn(src[6], src[7]);
        uint4 o;
        o.x = *reinterpret_cast<const uint32_t*>(&h0);
        o.y = *reinterpret_cast<const uint32_t*>(&h1);
        o.z = *reinterpret_cast<const uint32_t*>(&h2);
        o.w = *reinterpret_cast<const uint32_t*>(&h3);
        *reinterpret_cast<uint4*>(op + wv * 64 + cg * 8) = o;
    }
}

// ---------------------------------------------------------------------------
// Main kernel: one CTA (256 thr, 8 warps) per (ho, n) output row.
// Software-pipelined: LDGs for tap k+1 in flight under tap k's LDSM/HMMA.
// ---------------------------------------------------------------------------
constexpr int SMEM_A0   = 0;
constexpr int SMEM_A1   = 16384;
constexpr int SMEM_W    = 34816;                 // EPI f32 reuses [0, 33792)
constexpr int SMEM_POFF = 34816 + 73728;         // 108544, 1152 * 16B
constexpr int SMEM_PWH  = 108544 + 18432;        // 126976, 1152 * 8B
constexpr int SMEM_BYTES = 126976 + 9216;        // 136192 (~133 KB) -> 1 CTA/SM

__global__ void __launch_bounds__(256, 1)
main_kernel(const float* __restrict__ offset, float* __restrict__ out) {
    extern __shared__ char smem[];
    const uint32_t sb = smem_u32(smem);
    const int t = threadIdx.x;
    const int lane = t & 31, w = t >> 5;
    const int ho = blockIdx.x, n = blockIdx.y;

    // Stage all 9 pre-swizzled weight tiles (72 KB) into smem
    {
        const uint4* src = reinterpret_cast<const uint4*>(g_wh);
        uint4* dst = reinterpret_cast<uint4*>(smem + SMEM_W);
        for (int i = t; i < 73728 / 16; i += 256) dst[i] = src[i];
    }

    // Precompute per-(tap,pixel): 4 clamped corner byte-offsets + 4 masked fp16 weights
    int4*  POFF = reinterpret_cast<int4*>(smem + SMEM_POFF);
    uint2* PWH  = reinterpret_cast<uint2*>(smem + SMEM_PWH);
    for (int idx = t; idx < 1152; idx += 256) {
        const int k = idx >> 7, p = idx & 127;
        const int ob = ((n * 18 + 2 * k) * 128 + ho) * 128 + p;
        const float oy = __ldg(offset + ob);
        const float ox = __ldg(offset + ob + HW);
        const float py = (float)(ho + k / 3 - 1) + oy;
        const float px = (float)(p + k % 3 - 1) + ox;
        const float fy = floorf(py), fx = floorf(px);
        const float dy = py - fy, dx = px - fx;
        const int y0 = (int)fy, x0 = (int)fx;
        float wv[4]; int ofs[4];
#pragma unroll
        for (int cn = 0; cn < 4; cn++) {
            const int yy = y0 + (cn >> 1), xx = x0 + (cn & 1);
            float ww = ((cn >> 1) ? dy : 1.f - dy) * ((cn & 1) ? dx : 1.f - dx);
            const bool valid = ((unsigned)yy < 128u) && ((unsigned)xx < 128u);
            wv[cn] = valid ? ww : 0.f;
            const int yc = min(max(yy, 0), 127), xc = min(max(xx, 0), 127);
            ofs[cn] = (yc * 128 + xc) * 128;     // byte offset into NHWC fp16 image
        }
        POFF[idx] = make_int4(ofs[0], ofs[1], ofs[2], ofs[3]);
        const half2 wlo = __floats2half2_rn(wv[0], wv[1]);
        const half2 whi = __floats2half2_rn(wv[2], wv[3]);
        uint2 pw;
        pw.x = *reinterpret_cast<const uint32_t*>(&wlo);
        pw.y = *reinterpret_cast<const uint32_t*>(&whi);
        PWH[idx] = pw;
    }
    __syncthreads();

    const char* xbb = reinterpret_cast<const char*>(g_xh + (size_t)n * (128 * 128 * 64));
    const int c = t & 7;                          // 16B chunk within pixel line

    // ldmatrix lane addressing (SW128 xor depends only on row low bits)
    const int lt = lane >> 3, lr = lane & 7;
    const int rowA = 16 * w + (lt & 1) * 8 + lr;
    const uint32_t xrA = (uint32_t)(rowA & 7) << 4;
    const int rowB = (lt & 1) * 8 + lr;
    const uint32_t xrB = (uint32_t)(rowB & 7) << 4;
    const uint32_t cgrp = (uint32_t)(lt >> 1) * 16;
    const uint32_t aRow = (uint32_t)rowA * 128;
    const uint32_t bRow = (uint32_t)rowB * 128;

    float acc[8][4];
#pragma unroll
    for (int i = 0; i < 8; i++)
#pragma unroll
        for (int j = 0; j < 4; j++) acc[i][j] = 0.f;

    uint4 v[4][4];
    uint2 wh4[4];

    // Pipeline stage helpers
    auto gather_issue = [&](int k) {
        const int pbase = k << 7;
#pragma unroll
        for (int a = 0; a < 4; a++) {
            const int p = (a * 256 + t) >> 3;
            const int4 ofs = POFF[pbase + p];
            wh4[a] = PWH[pbase + p];
            v[a][0] = *reinterpret_cast<const uint4*>(xbb + ofs.x + c * 16);
            v[a][1] = *reinterpret_cast<const uint4*>(xbb + ofs.y + c * 16);
            v[a][2] = *reinterpret_cast<const uint4*>(xbb + ofs.z + c * 16);
            v[a][3] = *reinterpret_cast<const uint4*>(xbb + ofs.w + c * 16);
        }
    };

    auto bilinear_store = [&](char* abufp) {
#pragma unroll
        for (int a = 0; a < 4; a++) {
            const int p = (a * 256 + t) >> 3;
            const half2 wlo = *reinterpret_cast<const half2*>(&wh4[a].x);
            const half2 whi = *reinterpret_cast<const half2*>(&wh4[a].y);
            const half2 w00 = __low2half2(wlo),  w01 = __high2half2(wlo);
            const half2 w10 = __low2half2(whi),  w11 = __high2half2(whi);
            const half2* q0 = reinterpret_cast<const half2*>(&v[a][0]);
            const half2* q1 = reinterpret_cast<const half2*>(&v[a][1]);
            const half2* q2 = reinterpret_cast<const half2*>(&v[a][2]);
            const half2* q3 = reinterpret_cast<const half2*>(&v[a][3]);
            half2 s[4];
#pragma unroll
            for (int j = 0; j < 4; j++) {
                s[j] = __hmul2(w00, q0[j]);
                s[j] = __hfma2(w01, q1[j], s[j]);
                s[j] = __hfma2(w10, q2[j], s[j]);
                s[j] = __hfma2(w11, q3[j], s[j]);
            }
            uint32_t boff = (uint32_t)(p * 128 + c * 16);
            boff ^= (boff >> 3) & 0x70;
            uint4 ov;
            ov.x = *reinterpret_cast<const uint32_t*>(&s[0]);
            ov.y = *reinterpret_cast<const uint32_t*>(&s[1]);
            ov.z = *reinterpret_cast<const uint32_t*>(&s[2]);
            ov.w = *reinterpret_cast<const uint32_t*>(&s[3]);
            *reinterpret_cast<uint4*>(abufp + boff) = ov;
        }
    };

    auto mma_tap = [&](int k, uint32_t abuf) {
        const uint32_t wk = sb + SMEM_W + k * 8192;
#pragma unroll
        for (int kc = 0; kc < 4; kc++) {
            const uint32_t byte = (uint32_t)(kc * 32) + cgrp;
            uint32_t a0, a1, a2, a3;
            LDSM4(a0, a1, a2, a3, abuf + aRow + (byte ^ xrA));
            const uint32_t bb = byte ^ xrB;
#pragma unroll
            for (int j = 0; j < 4; j++) {
                uint32_t b0, b1, b2, b3;
                LDSM4(b0, b1, b2, b3, wk + bRow + (uint32_t)j * 2048 + bb);
                MMA16816(acc[2 * j],     a0, a1, a2, a3, b0, b2);
                MMA16816(acc[2 * j + 1], a0, a1, a2, a3, b1, b3);
            }
        }
    };

    // Prologue of the pipeline: fill buffer 0 with tap 0
    gather_issue(0);
    bilinear_store(smem + SMEM_A0);
    __syncthreads();

#pragma unroll 1
    for (int k = 0; k < 9; k++) {
        if (k < 8) gather_issue(k + 1);                  // LDGs in flight under MMA
        mma_tap(k, sb + ((k & 1) ? SMEM_A1 : SMEM_A0));  // tensor/shared phase
        if (k < 8) bilinear_store(smem + (((k + 1) & 1) ? SMEM_A1 : SMEM_A0));
        __syncthreads();
    }

    // ---- epilogue: scale, transpose through smem, coalesced float4 stores ----
    const float scale = g_scale;
    float* EPI = reinterpret_cast<float*>(smem);      // [64 cout][pitch 132]
    const int gr = lane >> 2, ci2 = (lane & 3) * 2, p0 = 16 * w;
#pragma unroll
    for (int nb = 0; nb < 8; nb++) {
        const int co = nb * 8 + ci2;
        EPI[co * 132 + p0 + gr]           = acc[nb][0] * scale;
        EPI[(co + 1) * 132 + p0 + gr]     = acc[nb][1] * scale;
        EPI[co * 132 + p0 + gr + 8]       = acc[nb][2] * scale;
        EPI[(co + 1) * 132 + p0 + gr + 8] = acc[nb][3] * scale;
    }
    __syncthreads();
    float* op = out + (size_t)n * 64 * HW + ho * 128;
#pragma unroll
    for (int r = 0; r < 8; r++) {
        const int idx = r * 256 + t;                  // 2048 float4 = 64 couts x 32
        const int co = idx >> 5, p4 = (idx & 31) * 4;
        const float4 vv = *reinterpret_cast<const float4*>(EPI + co * 132 + p4);
        *reinterpret_cast<float4*>(op + co * HW + p4) = vv;
    }
}

// ---------------------------------------------------------------------------
extern "C" void kernel_launch(void* const* d_in, const int* in_sizes, int n_in,
                              void* d_out, int out_size) {
    const float* x      = (const float*)d_in[0];
    const float* offset = (const float*)d_in[1];
    const float* weight = (const float*)d_in[2];
    float* out = (float*)d_out;

    cudaFuncSetAttribute(main_kernel, cudaFuncAttributeMaxDynamicSharedMemorySize,
                         SMEM_BYTES);

    absmax_kernel<<<1, 1024>>>(weight);
    wconv_kernel<<<(WELEMS + 255) / 256, 256>>>(weight);
    xcvt_kernel<<<dim3(HH, NB), 256>>>(x);
    main_kernel<<<dim3(HH, NB), 256, SMEM_BYTES>>>(offset, out);
}

// round 8
// speedup vs baseline: 6.5858x; 1.3970x over previous
#include <cuda_runtime.h>
#include <cuda_fp16.h>
#include <cstdint>
#include <cstring>

// ---------------------------------------------------------------------------
// Problem constants
// ---------------------------------------------------------------------------
constexpr int NB   = 8;
constexpr int HH   = 128;
constexpr int HW   = 128 * 128;           // 16384
constexpr int WELEMS = 64 * 64 * 9;       // 36864

// Scratch (device globals — allocation-free rule)
__device__ __half g_xh[NB * HH * 128 * 64];   // x as NHWC fp16 (16.8 MB)
__device__ __half g_wh[9 * 64 * 64];          // quantized int weights fp16, SW128-swizzled 8KB/tap
__device__ float  g_scale;

// ---------------------------------------------------------------------------
// Helpers
// ---------------------------------------------------------------------------
__device__ __forceinline__ uint32_t smem_u32(const void* p) {
    uint32_t a;
    asm("{ .reg .u64 t; cvta.to.shared.u64 t, %1; cvt.u32.u64 %0, t; }" : "=r"(a) : "l"(p));
    return a;
}

#define LDSM4(r0, r1, r2, r3, addr)                                           \
    asm volatile("ldmatrix.sync.aligned.m8n8.x4.shared.b16 {%0,%1,%2,%3}, [%4];" \
                 : "=r"(r0), "=r"(r1), "=r"(r2), "=r"(r3) : "r"(addr))

#define MMA16816(d, a0, a1, a2, a3, b0, b1)                                   \
    asm volatile("mma.sync.aligned.m16n8k16.row.col.f32.f16.f16.f32 "         \
                 "{%0,%1,%2,%3},{%4,%5,%6,%7},{%8,%9},{%0,%1,%2,%3};"          \
                 : "+f"((d)[0]), "+f"((d)[1]), "+f"((d)[2]), "+f"((d)[3])      \
                 : "r"(a0), "r"(a1), "r"(a2), "r"(a3), "r"(b0), "r"(b1))

#define CPASYNC16(dst, src)                                                   \
    asm volatile("cp.async.cg.shared.global [%0], [%1], 16;"                  \
                 :: "r"(dst), "l"(src) : "memory")
#define CPASYNC_COMMIT() asm volatile("cp.async.commit_group;" ::: "memory")
#define CPASYNC_WAIT0()  asm volatile("cp.async.wait_group 0;"  ::: "memory")

// ---------------------------------------------------------------------------
// Prologue kernel 1: absmax + scale (single block)
// ---------------------------------------------------------------------------
__global__ void absmax_kernel(const float* __restrict__ w) {
    __shared__ float red[1024];
    const int t = threadIdx.x;
    const float4* w4 = reinterpret_cast<const float4*>(w);
    float m = 0.f;
    for (int i = t; i < WELEMS / 4; i += 1024) {
        const float4 v = __ldg(w4 + i);
        m = fmaxf(m, fmaxf(fmaxf(fabsf(v.x), fabsf(v.y)), fmaxf(fabsf(v.z), fabsf(v.w))));
    }
    red[t] = m;
    __syncthreads();
    for (int s = 512; s > 0; s >>= 1) {
        if (t < s) red[t] = fmaxf(red[t], red[t + s]);
        __syncthreads();
    }
    if (t == 0) g_scale = fmaxf(red[0], 1e-8f) / 127.f;
}

// Prologue kernel 2: quantize + relayout (SW128-swizzled, [k][cout row][cin])
__global__ void wconv_kernel(const float* __restrict__ w) {
    const float scale = g_scale;
    const int i = blockIdx.x * 256 + threadIdx.x;
    if (i >= WELEMS) return;
    float q = rintf(w[i] / scale);                 // round-half-even = jnp.round
    q = fminf(fmaxf(q, -128.f), 127.f);            // integer, exact in fp16
    const int k = i % 9, ci = (i / 9) % 64, co = i / 576;
    uint32_t off = (uint32_t)(co * 128 + ci * 2);  // B tile: row=cout(128B), col=cin
    off ^= (off >> 3) & 0x70;                      // SW128 swizzle
    g_wh[(k * 8192 + off) >> 1] = __float2half_rn(q);
}

// Prologue kernel 3: x [N,C,H,W] f32 -> g_xh [N,H,W,C] fp16 (vectorized)
__global__ void xcvt_kernel(const float* __restrict__ x) {
    __shared__ float tb[128 * 65];
    const int h = blockIdx.x, n = blockIdx.y, t = threadIdx.x;
    const float* xp = x + (size_t)n * 64 * HW + h * 128;
    for (int i = t; i < 2048; i += 256) {          // 64c x 32 float4, coalesced
        const int c = i >> 5, q = i & 31;
        const float4 v = __ldg(reinterpret_cast<const float4*>(xp + c * HW) + q);
        float* tq = tb + (q * 4) * 65 + c;
        tq[0] = v.x; tq[65] = v.y; tq[130] = v.z; tq[195] = v.w;
    }
    __syncthreads();
    __half* op = g_xh + ((size_t)n * 128 + h) * 128 * 64;
    for (int i = t; i < 1024; i += 256) {          // 128w x 8 groups of 8 channels
        const int wv = i >> 3, cg = i & 7;
        const float* src = tb + wv * 65 + cg * 8;
        const half2 h0 = __floats2half2_rn(src[0], src[1]);
        const half2 h1 = __floats2half2_rn(src[2], src[3]);
        const half2 h2 = __floats2half2_rn(src[4], src[5]);
        const half2 h3 = __floats2half2_rn(src[6], src[7]);
        uint4 o;
        o.x = *reinterpret_cast<const uint32_t*>(&h0);
        o.y = *reinterpret_cast<const uint32_t*>(&h1);
        o.z = *reinterpret_cast<const uint32_t*>(&h2);
        o.w = *reinterpret_cast<const uint32_t*>(&h3);
        *reinterpret_cast<uint4*>(op + wv * 64 + cg * 8) = o;
    }
}

// ---------------------------------------------------------------------------
// Main kernel: one CTA (256 thr) per (ho, n) row; 2 CTAs / SM.
// Per-tap pipeline; W tap tiles double-buffered via cp.async from L2.
// ---------------------------------------------------------------------------
constexpr int SMEM_A0   = 0;                     // 16384
constexpr int SMEM_A1   = 16384;                 // 16384
constexpr int SMEM_WB0  = 32768;                 // 8192
constexpr int SMEM_WB1  = 40960;                 // 8192
constexpr int SMEM_POFF = 49152;                 // 1152 * 16B = 18432
constexpr int SMEM_PWH  = 67584;                 // 1152 * 8B  = 9216
constexpr int SMEM_BYTES = 76800;                // 75 KB -> 2 CTAs/SM (150 KB)

__global__ void __launch_bounds__(256, 2)
main_kernel(const float* __restrict__ offset, float* __restrict__ out) {
    extern __shared__ char smem[];
    const uint32_t sb = smem_u32(smem);
    const int t = threadIdx.x;
    const int lane = t & 31, w = t >> 5;
    const int ho = blockIdx.x, n = blockIdx.y;

    const char* whb = reinterpret_cast<const char*>(g_wh);

    // Prefetch W tap 0 into WB0 (32 B per thread)
    CPASYNC16(sb + SMEM_WB0 + t * 32,      whb + t * 32);
    CPASYNC16(sb + SMEM_WB0 + t * 32 + 16, whb + t * 32 + 16);
    CPASYNC_COMMIT();

    // Precompute per-(tap,pixel): 4 clamped corner byte-offsets + 4 masked fp16 weights
    int4*  POFF = reinterpret_cast<int4*>(smem + SMEM_POFF);
    uint2* PWH  = reinterpret_cast<uint2*>(smem + SMEM_PWH);
    for (int idx = t; idx < 1152; idx += 256) {
        const int k = idx >> 7, p = idx & 127;
        const int ob = ((n * 18 + 2 * k) * 128 + ho) * 128 + p;
        const float oy = __ldg(offset + ob);
        const float ox = __ldg(offset + ob + HW);
        const float py = (float)(ho + k / 3 - 1) + oy;
        const float px = (float)(p + k % 3 - 1) + ox;
        const float fy = floorf(py), fx = floorf(px);
        const float dy = py - fy, dx = px - fx;
        const int y0 = (int)fy, x0 = (int)fx;
        float wv[4]; int ofs[4];
#pragma unroll
        for (int cn = 0; cn < 4; cn++) {
            const int yy = y0 + (cn >> 1), xx = x0 + (cn & 1);
            float ww = ((cn >> 1) ? dy : 1.f - dy) * ((cn & 1) ? dx : 1.f - dx);
            const bool valid = ((unsigned)yy < 128u) && ((unsigned)xx < 128u);
            wv[cn] = valid ? ww : 0.f;
            const int yc = min(max(yy, 0), 127), xc = min(max(xx, 0), 127);
            ofs[cn] = (yc * 128 + xc) * 128;     // byte offset into NHWC fp16 image
        }
        POFF[idx] = make_int4(ofs[0], ofs[1], ofs[2], ofs[3]);
        const half2 wlo = __floats2half2_rn(wv[0], wv[1]);
        const half2 whi = __floats2half2_rn(wv[2], wv[3]);
        uint2 pw;
        pw.x = *reinterpret_cast<const uint32_t*>(&wlo);
        pw.y = *reinterpret_cast<const uint32_t*>(&whi);
        PWH[idx] = pw;
    }
    __syncthreads();

    const char* xbb = reinterpret_cast<const char*>(g_xh + (size_t)n * (128 * 128 * 64));
    const int c = t & 7;                          // 16B chunk within pixel line

    // ldmatrix lane addressing (SW128 xor depends only on row low bits)
    const int lt = lane >> 3, lr = lane & 7;
    const int rowA = 16 * w + (lt & 1) * 8 + lr;
    const uint32_t xrA = (uint32_t)(rowA & 7) << 4;
    const int rowB = (lt & 1) * 8 + lr;
    const uint32_t xrB = (uint32_t)(rowB & 7) << 4;
    const uint32_t cgrp = (uint32_t)(lt >> 1) * 16;
    const uint32_t aRow = (uint32_t)rowA * 128;
    const uint32_t bRow = (uint32_t)rowB * 128;

    float acc[8][4];
#pragma unroll
    for (int i = 0; i < 8; i++)
#pragma unroll
        for (int j = 0; j < 4; j++) acc[i][j] = 0.f;

    uint4 v[2][4];          // one gather half in flight (32 regs)
    uint2 wh2[2];

    auto gather_half = [&](int k, int h0) {
        const int pbase = k << 7;
#pragma unroll
        for (int a = 0; a < 2; a++) {
            const int p = ((h0 + a) * 256 + t) >> 3;
            const int4 ofs = POFF[pbase + p];
            wh2[a] = PWH[pbase + p];
            v[a][0] = *reinterpret_cast<const uint4*>(xbb + ofs.x + c * 16);
            v[a][1] = *reinterpret_cast<const uint4*>(xbb + ofs.y + c * 16);
            v[a][2] = *reinterpret_cast<const uint4*>(xbb + ofs.z + c * 16);
            v[a][3] = *reinterpret_cast<const uint4*>(xbb + ofs.w + c * 16);
        }
    };

    auto bilinear_half = [&](char* abufp, int h0) {
#pragma unroll
        for (int a = 0; a < 2; a++) {
            const int p = ((h0 + a) * 256 + t) >> 3;
            const half2 wlo = *reinterpret_cast<const half2*>(&wh2[a].x);
            const half2 whi = *reinterpret_cast<const half2*>(&wh2[a].y);
            const half2 w00 = __low2half2(wlo),  w01 = __high2half2(wlo);
            const half2 w10 = __low2half2(whi),  w11 = __high2half2(whi);
            const half2* q0 = reinterpret_cast<const half2*>(&v[a][0]);
            const half2* q1 = reinterpret_cast<const half2*>(&v[a][1]);
            const half2* q2 = reinterpret_cast<const half2*>(&v[a][2]);
            const half2* q3 = reinterpret_cast<const half2*>(&v[a][3]);
            half2 s[4];
#pragma unroll
            for (int j = 0; j < 4; j++) {
                s[j] = __hmul2(w00, q0[j]);
                s[j] = __hfma2(w01, q1[j], s[j]);
                s[j] = __hfma2(w10, q2[j], s[j]);
                s[j] = __hfma2(w11, q3[j], s[j]);
            }
            uint32_t boff = (uint32_t)(p * 128 + c * 16);
            boff ^= (boff >> 3) & 0x70;
            uint4 ov;
            ov.x = *reinterpret_cast<const uint32_t*>(&s[0]);
            ov.y = *reinterpret_cast<const uint32_t*>(&s[1]);
            ov.z = *reinterpret_cast<const uint32_t*>(&s[2]);
            ov.w = *reinterpret_cast<const uint32_t*>(&s[3]);
            *reinterpret_cast<uint4*>(abufp + boff) = ov;
        }
    };

    auto mma_tap = [&](uint32_t abuf, uint32_t wk) {
#pragma unroll
        for (int kc = 0; kc < 4; kc++) {
            const uint32_t byte = (uint32_t)(kc * 32) + cgrp;
            uint32_t a0, a1, a2, a3;
            LDSM4(a0, a1, a2, a3, abuf + aRow + (byte ^ xrA));
            const uint32_t bb = byte ^ xrB;
#pragma unroll
            for (int j = 0; j < 4; j++) {
                uint32_t b0, b1, b2, b3;
                LDSM4(b0, b1, b2, b3, wk + bRow + (uint32_t)j * 2048 + bb);
                MMA16816(acc[2 * j],     a0, a1, a2, a3, b0, b2);
                MMA16816(acc[2 * j + 1], a0, a1, a2, a3, b1, b3);
            }
        }
    };

    // Pipeline prologue: fill A buffer 0 with tap 0 (two halves)
    gather_half(0, 0);
    bilinear_half(smem + SMEM_A0, 0);
    gather_half(0, 2);
    bilinear_half(smem + SMEM_A0, 2);
    CPASYNC_WAIT0();            // W tap 0 resident
    __syncthreads();

#pragma unroll 1
    for (int k = 0; k < 9; k++) {
        const uint32_t wk  = sb + ((k & 1) ? SMEM_WB1 : SMEM_WB0);
        char* anext = smem + (((k + 1) & 1) ? SMEM_A1 : SMEM_A0);
        if (k < 8) {
            // prefetch W(k+1) under this tap's MMA
            const uint32_t wdst = sb + (((k + 1) & 1) ? SMEM_WB1 : SMEM_WB0) + t * 32;
            const char* wsrc = whb + (k + 1) * 8192 + t * 32;
            CPASYNC16(wdst, wsrc);
            CPASYNC16(wdst + 16, wsrc + 16);
            CPASYNC_COMMIT();
            gather_half(k + 1, 0);                  // LDGs in flight under MMA
        }
        mma_tap(sb + ((k & 1) ? SMEM_A1 : SMEM_A0), wk);
        if (k < 8) {
            bilinear_half(anext, 0);
            gather_half(k + 1, 2);
            bilinear_half(anext, 2);
            CPASYNC_WAIT0();
        }
        __syncthreads();
    }

    // ---- epilogue: scale, transpose through smem, coalesced float4 stores ----
    const float scale = g_scale;
    float* EPI = reinterpret_cast<float*>(smem);      // [64 cout][pitch 132] = 33792 B
    const int gr = lane >> 2, ci2 = (lane & 3) * 2, p0 = 16 * w;
#pragma unroll
    for (int nb = 0; nb < 8; nb++) {
        const int co = nb * 8 + ci2;
        EPI[co * 132 + p0 + gr]           = acc[nb][0] * scale;
        EPI[(co + 1) * 132 + p0 + gr]     = acc[nb][1] * scale;
        EPI[co * 132 + p0 + gr + 8]       = acc[nb][2] * scale;
        EPI[(co + 1) * 132 + p0 + gr + 8] = acc[nb][3] * scale;
    }
    __syncthreads();
    float* op = out + (size_t)n * 64 * HW + ho * 128;
#pragma unroll
    for (int r = 0; r < 8; r++) {
        const int idx = r * 256 + t;                  // 2048 float4 = 64 couts x 32
        const int co = idx >> 5, p4 = (idx & 31) * 4;
        const float4 vv = *reinterpret_cast<const float4*>(EPI + co * 132 + p4);
        *reinterpret_cast<float4*>(op + co * HW + p4) = vv;
    }
}

// ---------------------------------------------------------------------------
extern "C" void kernel_launch(void* const* d_in, const int* in_sizes, int n_in,
                              void* d_out, int out_size) {
    const float* x      = (const float*)d_in[0];
    const float* offset = (const float*)d_in[1];
    const float* weight = (const float*)d_in[2];
    float* out = (float*)d_out;

    cudaFuncSetAttribute(main_kernel, cudaFuncAttributeMaxDynamicSharedMemorySize,
                         SMEM_BYTES);

    absmax_kernel<<<1, 1024>>>(weight);
    wconv_kernel<<<(WELEMS + 255) / 256, 256>>>(weight);
    xcvt_kernel<<<dim3(HH, NB), 256>>>(x);
    main_kernel<<<dim3(HH, NB), 256, SMEM_BYTES>>>(offset, out);
}

// round 9
// speedup vs baseline: 6.9463x; 1.0547x over previous
#include <cuda_runtime.h>
#include <cuda_fp16.h>
#include <cstdint>
#include <cstring>

// ---------------------------------------------------------------------------
// Problem constants
// ---------------------------------------------------------------------------
constexpr int NB   = 8;
constexpr int HH   = 128;
constexpr int HW   = 128 * 128;           // 16384
constexpr int WELEMS = 64 * 64 * 9;       // 36864
constexpr int PAD_H = 8256;               // 16512 B halo (one row + one pixel)

// Scratch (device globals — allocation-free rule). Zero-initialized halos:
// derived corner reads with weight==0 may land there; zeros are finite.
__device__ __half g_xa[PAD_H + NB * HW * 64 + PAD_H];
__device__ __half g_wh[9 * 64 * 64];      // int-valued fp16 weights, SW128-swizzled 8KB/tap
__device__ float  g_scale;

// ---------------------------------------------------------------------------
// Helpers
// ---------------------------------------------------------------------------
__device__ __forceinline__ uint32_t smem_u32(const void* p) {
    uint32_t a;
    asm("{ .reg .u64 t; cvta.to.shared.u64 t, %1; cvt.u32.u64 %0, t; }" : "=r"(a) : "l"(p));
    return a;
}

#define LDSM4(r0, r1, r2, r3, addr)                                           \
    asm volatile("ldmatrix.sync.aligned.m8n8.x4.shared.b16 {%0,%1,%2,%3}, [%4];" \
                 : "=r"(r0), "=r"(r1), "=r"(r2), "=r"(r3) : "r"(addr))

#define MMA16816(d, a0, a1, a2, a3, b0, b1)                                   \
    asm volatile("mma.sync.aligned.m16n8k16.row.col.f32.f16.f16.f32 "         \
                 "{%0,%1,%2,%3},{%4,%5,%6,%7},{%8,%9},{%0,%1,%2,%3};"          \
                 : "+f"((d)[0]), "+f"((d)[1]), "+f"((d)[2]), "+f"((d)[3])      \
                 : "r"(a0), "r"(a1), "r"(a2), "r"(a3), "r"(b0), "r"(b1))

#define CPASYNC16(dst, src)                                                   \
    asm volatile("cp.async.cg.shared.global [%0], [%1], 16;"                  \
                 :: "r"(dst), "l"(src) : "memory")
#define CPASYNC_COMMIT() asm volatile("cp.async.commit_group;" ::: "memory")
#define CPASYNC_WAIT0()  asm volatile("cp.async.wait_group 0;"  ::: "memory")

// ---------------------------------------------------------------------------
// Prologue kernel 1: fused absmax (redundant per-block, deterministic) +
// quantize + relayout (SW128-swizzled, [k][cout row][cin])
// ---------------------------------------------------------------------------
__global__ void wconv_kernel(const float* __restrict__ w) {
    __shared__ float red[256];
    const int t = threadIdx.x;
    const float4* w4 = reinterpret_cast<const float4*>(w);
    float m = 0.f;
    for (int i = t; i < WELEMS / 4; i += 256) {
        const float4 v = __ldg(w4 + i);
        m = fmaxf(m, fmaxf(fmaxf(fabsf(v.x), fabsf(v.y)), fmaxf(fabsf(v.z), fabsf(v.w))));
    }
    red[t] = m;
    __syncthreads();
    for (int s = 128; s > 0; s >>= 1) {
        if (t < s) red[t] = fmaxf(red[t], red[t + s]);
        __syncthreads();
    }
    const float scale = fmaxf(red[0], 1e-8f) / 127.f;   // identical in every block
    const int i = blockIdx.x * 256 + t;
    if (i == 0) g_scale = scale;
    if (i >= WELEMS) return;
    float q = rintf(w[i] / scale);                 // round-half-even = jnp.round
    q = fminf(fmaxf(q, -128.f), 127.f);            // integer, exact in fp16
    const int k = i % 9, ci = (i / 9) % 64, co = i / 576;
    uint32_t off = (uint32_t)(co * 128 + ci * 2);  // B tile: row=cout(128B), col=cin
    off ^= (off >> 3) & 0x70;                      // SW128 swizzle
    g_wh[(k * 8192 + off) >> 1] = __float2half_rn(q);
}

// Prologue kernel 2: x [N,C,H,W] f32 -> NHWC fp16 (vectorized)
__global__ void xcvt_kernel(const float* __restrict__ x) {
    __shared__ float tb[128 * 65];
    const int h = blockIdx.x, n = blockIdx.y, t = threadIdx.x;
    const float* xp = x + (size_t)n * 64 * HW + h * 128;
    for (int i = t; i < 2048; i += 256) {          // 64c x 32 float4, coalesced
        const int c = i >> 5, q = i & 31;
        const float4 v = __ldg(reinterpret_cast<const float4*>(xp + c * HW) + q);
        float* tq = tb + (q * 4) * 65 + c;
        tq[0] = v.x; tq[65] = v.y; tq[130] = v.z; tq[195] = v.w;
    }
    __syncthreads();
    __half* op = g_xa + PAD_H + ((size_t)n * 128 + h) * 128 * 64;
    for (int i = t; i < 1024; i += 256) {          // 128w x 8 groups of 8 channels
        const int wv = i >> 3, cg = i & 7;
        const float* src = tb + wv * 65 + cg * 8;
        const half2 h0 = __floats2half2_rn(src[0], src[1]);
        const half2 h1 = __floats2half2_rn(src[2], src[3]);
        const half2 h2 = __floats2half2_rn(src[4], src[5]);
        const half2 h3 = __floats2half2_rn(src[6], src[7]);
        uint4 o;
        o.x = *reinterpret_cast<const uint32_t*>(&h0);
        o.y = *reinterpret_cast<const uint32_t*>(&h1);
        o.z = *reinterpret_cast<const uint32_t*>(&h2);
        o.w = *reinterpret_cast<const uint32_t*>(&h3);
        *reinterpret_cast<uint4*>(op + wv * 64 + cg * 8) = o;
    }
}

// ---------------------------------------------------------------------------
// Main kernel: one CTA (256 thr) per (ho, n) row; 2 CTAs / SM, ~102 KB L1D.
// Per-tap pipeline; W tap tiles double-buffered via cp.async from L2.
// Warp tiling: 32 pix x 32 cout (16 LDSM/warp/tap).
// ---------------------------------------------------------------------------
constexpr int SMEM_A0   = 0;                     // 16384
constexpr int SMEM_A1   = 16384;                 // 16384
constexpr int SMEM_WB0  = 32768;                 // 8192
constexpr int SMEM_WB1  = 40960;                 // 8192
constexpr int SMEM_POFF = 49152;                 // 1152 * 4B  = 4608
constexpr int SMEM_PWH  = 53760;                 // 1152 * 8B  = 9216
constexpr int SMEM_BYTES = 62976;                // 61.5 KB -> 2 CTAs/SM

__global__ void __launch_bounds__(256, 2)
main_kernel(const float* __restrict__ offset, float* __restrict__ out) {
    extern __shared__ char smem[];
    const uint32_t sb = smem_u32(smem);
    const int t = threadIdx.x;
    const int lane = t & 31, w = t >> 5;
    const int ho = blockIdx.x, n = blockIdx.y;

    const char* whb = reinterpret_cast<const char*>(g_wh);

    // Prefetch W tap 0 into WB0 (32 B per thread)
    CPASYNC16(sb + SMEM_WB0 + t * 32,      whb + t * 32);
    CPASYNC16(sb + SMEM_WB0 + t * 32 + 16, whb + t * 32 + 16);
    CPASYNC_COMMIT();

    // Precompute per-(tap,pixel): clamped base corner offset + 4 masked fp16 weights.
    // Corners derived as off00 + {0, 128, 16384, 16512} bytes; invalid corners have
    // weight 0 and land in halos / neighboring finite data.
    int*   POFF = reinterpret_cast<int*>(smem + SMEM_POFF);
    uint2* PWH  = reinterpret_cast<uint2*>(smem + SMEM_PWH);
    for (int idx = t; idx < 1152; idx += 256) {
        const int k = idx >> 7, p = idx & 127;
        const int ob = ((n * 18 + 2 * k) * 128 + ho) * 128 + p;
        const float oy = __ldg(offset + ob);
        const float ox = __ldg(offset + ob + HW);
        const float py = (float)(ho + k / 3 - 1) + oy;
        const float px = (float)(p + k % 3 - 1) + ox;
        const float fy = floorf(py), fx = floorf(px);
        const float dy = py - fy, dx = px - fx;
        const int y0 = (int)fy, x0 = (int)fx;
        float wv[4];
#pragma unroll
        for (int cn = 0; cn < 4; cn++) {
            const int yy = y0 + (cn >> 1), xx = x0 + (cn & 1);
            float ww = ((cn >> 1) ? dy : 1.f - dy) * ((cn & 1) ? dx : 1.f - dx);
            const bool valid = ((unsigned)yy < 128u) && ((unsigned)xx < 128u);
            wv[cn] = valid ? ww : 0.f;
        }
        const int y0c = min(max(y0, -1), 127), x0c = min(max(x0, -1), 127);
        POFF[idx] = (y0c * 128 + x0c) * 128;           // byte offset (may be negative)
        const half2 wlo = __floats2half2_rn(wv[0], wv[1]);
        const half2 whi = __floats2half2_rn(wv[2], wv[3]);
        uint2 pw;
        pw.x = *reinterpret_cast<const uint32_t*>(&wlo);
        pw.y = *reinterpret_cast<const uint32_t*>(&whi);
        PWH[idx] = pw;
    }
    __syncthreads();

    const char* xbb = reinterpret_cast<const char*>(g_xa + PAD_H)
                    + (size_t)n * (128 * 128 * 128);   // image stride bytes
    const int c = t & 7;                               // 16B chunk within pixel line

    // ldmatrix lane addressing (SW128 xor depends only on row low bits)
    const int lt = lane >> 3, lr = lane & 7;
    const int pgrp = (w & 3) * 32;                     // pixel group of 32
    const int cb   = (w >> 2) * 32;                    // cout group of 32
    const int rsub = (lt & 1) * 8 + lr;                // 0..15
    const uint32_t xrr = (uint32_t)(rsub & 7) << 4;    // same for +16 rows
    const uint32_t cgrp16 = (uint32_t)(lt >> 1) * 16;
    const uint32_t aB0 = (uint32_t)(pgrp + rsub) * 128;
    const uint32_t aB1 = aB0 + 16 * 128;
    const uint32_t bB0 = (uint32_t)(cb + rsub) * 128;
    const uint32_t bB1 = bB0 + 16 * 128;

    float acc[2][4][4];
#pragma unroll
    for (int i = 0; i < 2; i++)
#pragma unroll
        for (int j = 0; j < 4; j++)
#pragma unroll
            for (int q = 0; q < 4; q++) acc[i][j][q] = 0.f;

    uint4 v[2][4];          // one gather half in flight (32 regs)
    uint2 wh2[2];

    auto gather_half = [&](int k, int h0) {
        const int pbase = k << 7;
#pragma unroll
        for (int a = 0; a < 2; a++) {
            const int p = ((h0 + a) * 256 + t) >> 3;
            const int o0 = POFF[pbase + p] + c * 16;
            wh2[a] = PWH[pbase + p];
            v[a][0] = *reinterpret_cast<const uint4*>(xbb + o0);
            v[a][1] = *reinterpret_cast<const uint4*>(xbb + o0 + 128);
            v[a][2] = *reinterpret_cast<const uint4*>(xbb + o0 + 16384);
            v[a][3] = *reinterpret_cast<const uint4*>(xbb + o0 + 16512);
        }
    };

    auto bilinear_half = [&](char* abufp, int h0) {
#pragma unroll
        for (int a = 0; a < 2; a++) {
            const int p = ((h0 + a) * 256 + t) >> 3;
            const half2 wlo = *reinterpret_cast<const half2*>(&wh2[a].x);
            const half2 whi = *reinterpret_cast<const half2*>(&wh2[a].y);
            const half2 w00 = __low2half2(wlo),  w01 = __high2half2(wlo);
            const half2 w10 = __low2half2(whi),  w11 = __high2half2(whi);
            const half2* q0 = reinterpret_cast<const half2*>(&v[a][0]);
            const half2* q1 = reinterpret_cast<const half2*>(&v[a][1]);
            const half2* q2 = reinterpret_cast<const half2*>(&v[a][2]);
            const half2* q3 = reinterpret_cast<const half2*>(&v[a][3]);
            half2 s[4];
#pragma unroll
            for (int j = 0; j < 4; j++) {
                s[j] = __hmul2(w00, q0[j]);
                s[j] = __hfma2(w01, q1[j], s[j]);
                s[j] = __hfma2(w10, q2[j], s[j]);
                s[j] = __hfma2(w11, q3[j], s[j]);
            }
            uint32_t boff = (uint32_t)(p * 128 + c * 16);
            boff ^= (boff >> 3) & 0x70;
            uint4 ov;
            ov.x = *reinterpret_cast<const uint32_t*>(&s[0]);
            ov.y = *reinterpret_cast<const uint32_t*>(&s[1]);
            ov.z = *reinterpret_cast<const uint32_t*>(&s[2]);
            ov.w = *reinterpret_cast<const uint32_t*>(&s[3]);
            *reinterpret_cast<uint4*>(abufp + boff) = ov;
        }
    };

    auto mma_tap = [&](uint32_t abuf, uint32_t wk) {
#pragma unroll
        for (int kc = 0; kc < 4; kc++) {
            const uint32_t byte = (uint32_t)(kc * 32) + cgrp16;
            const uint32_t bx = byte ^ xrr;
            uint32_t a0[4], a1[4];
            LDSM4(a0[0], a0[1], a0[2], a0[3], abuf + aB0 + bx);
            LDSM4(a1[0], a1[1], a1[2], a1[3], abuf + aB1 + bx);
#pragma unroll
            for (int nh = 0; nh < 2; nh++) {
                uint32_t b0, b1, b2, b3;
                LDSM4(b0, b1, b2, b3, wk + (nh ? bB1 : bB0) + bx);
                MMA16816(acc[0][nh * 2],     a0[0], a0[1], a0[2], a0[3], b0, b2);
                MMA16816(acc[0][nh * 2 + 1], a0[0], a0[1], a0[2], a0[3], b1, b3);
                MMA16816(acc[1][nh * 2],     a1[0], a1[1], a1[2], a1[3], b0, b2);
                MMA16816(acc[1][nh * 2 + 1], a1[0], a1[1], a1[2], a1[3], b1, b3);
            }
        }
    };

    // Pipeline prologue: fill A buffer 0 with tap 0 (two halves)
    gather_half(0, 0);
    bilinear_half(smem + SMEM_A0, 0);
    gather_half(0, 2);
    bilinear_half(smem + SMEM_A0, 2);
    CPASYNC_WAIT0();            // W tap 0 resident
    __syncthreads();

#pragma unroll 1
    for (int k = 0; k < 9; k++) {
        const uint32_t wk  = sb + ((k & 1) ? SMEM_WB1 : SMEM_WB0);
        char* anext = smem + (((k + 1) & 1) ? SMEM_A1 : SMEM_A0);
        if (k < 8) {
            // prefetch W(k+1) under this tap's MMA
            const uint32_t wdst = sb + (((k + 1) & 1) ? SMEM_WB1 : SMEM_WB0) + t * 32;
            const char* wsrc = whb + (k + 1) * 8192 + t * 32;
            CPASYNC16(wdst, wsrc);
            CPASYNC16(wdst + 16, wsrc + 16);
            CPASYNC_COMMIT();
            gather_half(k + 1, 0);                  // LDGs in flight under MMA
        }
        mma_tap(sb + ((k & 1) ? SMEM_A1 : SMEM_A0), wk);
        if (k < 8) {
            bilinear_half(anext, 0);
            gather_half(k + 1, 2);
            bilinear_half(anext, 2);
            CPASYNC_WAIT0();
        }
        __syncthreads();
    }

    // ---- epilogue: scale, transpose through smem, coalesced float4 stores ----
    const float scale = g_scale;
    float* EPI = reinterpret_cast<float*>(smem);      // [64 cout][pitch 132] = 33792 B
    const int gr = lane >> 2, ci2 = (lane & 3) * 2;
#pragma unroll
    for (int mt = 0; mt < 2; mt++)
#pragma unroll
        for (int nt = 0; nt < 4; nt++) {
            const int pix = pgrp + mt * 16 + gr;
            const int co  = cb + nt * 8 + ci2;
            EPI[co * 132 + pix]           = acc[mt][nt][0] * scale;
            EPI[(co + 1) * 132 + pix]     = acc[mt][nt][1] * scale;
            EPI[co * 132 + pix + 8]       = acc[mt][nt][2] * scale;
            EPI[(co + 1) * 132 + pix + 8] = acc[mt][nt][3] * scale;
        }
    __syncthreads();
    float* op = out + (size_t)n * 64 * HW + ho * 128;
#pragma unroll
    for (int r = 0; r < 8; r++) {
        const int idx = r * 256 + t;                  // 2048 float4 = 64 couts x 32
        const int co = idx >> 5, p4 = (idx & 31) * 4;
        const float4 vv = *reinterpret_cast<const float4*>(EPI + co * 132 + p4);
        *reinterpret_cast<float4*>(op + co * HW + p4) = vv;
    }
}

// ---------------------------------------------------------------------------
extern "C" void kernel_launch(void* const* d_in, const int* in_sizes, int n_in,
                              void* d_out, int out_size) {
    const float* x      = (const float*)d_in[0];
    const float* offset = (const float*)d_in[1];
    const float* weight = (const float*)d_in[2];
    float* out = (float*)d_out;

    cudaFuncSetAttribute(main_kernel, cudaFuncAttributeMaxDynamicSharedMemorySize,
                         SMEM_BYTES);

    wconv_kernel<<<(WELEMS + 255) / 256, 256>>>(weight);
    xcvt_kernel<<<dim3(HH, NB), 256>>>(x);
    main_kernel<<<dim3(HH, NB), 256, SMEM_BYTES>>>(offset, out);
}